// round 8
// baseline (speedup 1.0000x reference)
#include <cuda_runtime.h>
#include <math.h>
#include <stdint.h>

// Problem constants
#define B_    2
#define L_    13294
#define S_    13294
#define D_    256
#define NH_   8
#define HD_   32
#define M_    (B_ * L_)          // 26588 rows for all GEMMs

// Scratch (static device arrays — no allocation allowed)
__device__ float g_val   [(size_t)M_ * 256];  // value @ W_val    [B,S,NH,HD]
__device__ float g_offlog[(size_t)M_ * 384];  // query @ [W_off|W_attn]
__device__ float g_acc   [(size_t)M_ * 256];  // sampled output   [B,L,NH,HD]
__device__ float g_Wcat  [256 * 384];         // packed [W_off | W_attn]
__device__ float g_bcat  [384];               // packed [b_off | b_attn]

__device__ __forceinline__ uint32_t f2tf32(float f) {
    uint32_t u;
    asm("cvt.rna.tf32.f32 %0, %1;" : "=r"(u) : "f"(f));
    return u;
}

// ---------------------------------------------------------------------------
// Pack [W_off | W_attn] (K=256 rows) and biases into contiguous N=384 buffers.
// ---------------------------------------------------------------------------
__global__ void pack_qkw(const float* __restrict__ W_off,
                         const float* __restrict__ W_attn,
                         const float* __restrict__ b_off,
                         const float* __restrict__ b_attn,
                         float* __restrict__ Wcat, float* __restrict__ bcat) {
    const int i = blockIdx.x * blockDim.x + threadIdx.x;   // 256*384 threads
    const int k = i / 384;
    const int n = i % 384;
    Wcat[i] = (n < 256) ? W_off[k * 256 + n] : W_attn[k * 128 + (n - 256)];
    if (i < 384)
        bcat[i] = (i < 256) ? b_off[i] : b_attn[i - 256];
}

// ---------------------------------------------------------------------------
// tf32 tensor-core GEMM with bias: C[M,N] = A[M,K] @ W[K,N] + b[N]
// Block tile 128x128, BK=16, 256 threads = 8 warps, warp tile 64x32.
// Double-buffered smem: ONE __syncthreads per K-iteration.
// ---------------------------------------------------------------------------
__global__ __launch_bounds__(256, 2)
void gemm_tf32(const float* __restrict__ A, const float* __restrict__ W,
               const float* __restrict__ bias, float* __restrict__ C,
               int M, int N, int K) {
    __shared__ __align__(16) uint32_t As[2][128][20];
    __shared__ __align__(16) uint32_t Bs[2][16][132];

    const int t    = threadIdx.x;
    const int warp = t >> 5;
    const int lane = t & 31;
    const int g    = lane >> 2;
    const int tg   = lane & 3;
    const int wm   = (warp & 1) * 64;
    const int wn   = (warp >> 1) * 32;

    const int m0 = blockIdx.y * 128;
    const int n0 = blockIdx.x * 128;

    const int ar  = t >> 2;
    const int ak  = (t & 3) * 4;
    const int br  = t >> 5;
    const int bc  = (t & 31) * 4;

    float4 av0, av1, bv0, bv1;

    auto load_tiles = [&](int k0) {
        const float4 z = make_float4(0.f, 0.f, 0.f, 0.f);
        int r0 = m0 + ar;
        av0 = (r0 < M) ? *(const float4*)&A[(size_t)r0 * K + k0 + ak] : z;
        int r1 = r0 + 64;
        av1 = (r1 < M) ? *(const float4*)&A[(size_t)r1 * K + k0 + ak] : z;
        bv0 = *(const float4*)&W[(size_t)(k0 + br)     * N + n0 + bc];
        bv1 = *(const float4*)&W[(size_t)(k0 + br + 8) * N + n0 + bc];
    };
    auto store_tiles = [&](int buf) {
        uint4 u;
        u.x = f2tf32(av0.x); u.y = f2tf32(av0.y);
        u.z = f2tf32(av0.z); u.w = f2tf32(av0.w);
        *(uint4*)&As[buf][ar][ak] = u;
        u.x = f2tf32(av1.x); u.y = f2tf32(av1.y);
        u.z = f2tf32(av1.z); u.w = f2tf32(av1.w);
        *(uint4*)&As[buf][ar + 64][ak] = u;
        u.x = f2tf32(bv0.x); u.y = f2tf32(bv0.y);
        u.z = f2tf32(bv0.z); u.w = f2tf32(bv0.w);
        *(uint4*)&Bs[buf][br][bc] = u;
        u.x = f2tf32(bv1.x); u.y = f2tf32(bv1.y);
        u.z = f2tf32(bv1.z); u.w = f2tf32(bv1.w);
        *(uint4*)&Bs[buf][br + 8][bc] = u;
    };

    float acc[4][4][4];
#pragma unroll
    for (int i = 0; i < 4; i++)
#pragma unroll
        for (int j = 0; j < 4; j++)
#pragma unroll
            for (int r = 0; r < 4; r++) acc[i][j][r] = 0.f;

    const int niter = K / 16;
    load_tiles(0);
    store_tiles(0);
    __syncthreads();

    for (int it = 0; it < niter; ++it) {
        const int  buf  = it & 1;
        const bool more = (it + 1) < niter;
        if (more) load_tiles((it + 1) * 16);

#pragma unroll
        for (int ks = 0; ks < 2; ks++) {
            const int kb = ks * 8;
            uint32_t af[4][4], bf[4][2];
#pragma unroll
            for (int mt = 0; mt < 4; mt++) {
                const int r = wm + mt * 16 + g;
                af[mt][0] = As[buf][r    ][kb + tg];
                af[mt][1] = As[buf][r + 8][kb + tg];
                af[mt][2] = As[buf][r    ][kb + tg + 4];
                af[mt][3] = As[buf][r + 8][kb + tg + 4];
            }
#pragma unroll
            for (int nt = 0; nt < 4; nt++) {
                const int c = wn + nt * 8 + g;
                bf[nt][0] = Bs[buf][kb + tg    ][c];
                bf[nt][1] = Bs[buf][kb + tg + 4][c];
            }
#pragma unroll
            for (int mt = 0; mt < 4; mt++)
#pragma unroll
                for (int nt = 0; nt < 4; nt++) {
                    asm volatile(
                        "mma.sync.aligned.m16n8k8.row.col.f32.tf32.tf32.f32 "
                        "{%0,%1,%2,%3}, {%4,%5,%6,%7}, {%8,%9}, {%0,%1,%2,%3};"
                        : "+f"(acc[mt][nt][0]), "+f"(acc[mt][nt][1]),
                          "+f"(acc[mt][nt][2]), "+f"(acc[mt][nt][3])
                        : "r"(af[mt][0]), "r"(af[mt][1]),
                          "r"(af[mt][2]), "r"(af[mt][3]),
                          "r"(bf[nt][0]), "r"(bf[nt][1]));
                }
        }

        if (more) store_tiles(buf ^ 1);
        __syncthreads();
    }

#pragma unroll
    for (int nt = 0; nt < 4; nt++) {
        const int c = n0 + wn + nt * 8 + tg * 2;
        const float2 bb = *(const float2*)&bias[c];
#pragma unroll
        for (int mt = 0; mt < 4; mt++) {
            const int r0 = m0 + wm + mt * 16 + g;
            if (r0 < M) {
                float2 o = make_float2(acc[mt][nt][0] + bb.x,
                                       acc[mt][nt][1] + bb.y);
                *(float2*)&C[(size_t)r0 * N + c] = o;
            }
            const int r1 = r0 + 8;
            if (r1 < M) {
                float2 o = make_float2(acc[mt][nt][2] + bb.x,
                                       acc[mt][nt][3] + bb.y);
                *(float2*)&C[(size_t)r1 * N + c] = o;
            }
        }
    }
}

// ---------------------------------------------------------------------------
// Staged deformable sampling.
// Block = 32 (bq,h) pairs, 256 threads.
// Phase 1: 8 lanes/pair; each lane preps its 2 samples: softmax weight,
//   OOB-zeroed bilinear weights (premultiplied by softmax weight), and
//   clamped corner element-offsets -> smem (8 words/sample).
// Phase 2: warp = 4 pairs (8 lanes each, lane = 4 channels). Hot loop is
//   2x LDS.128 + 4x unconditional LDG.128 + 16 FFMA per sample. No shuffles,
//   no predicates, no floor in the gather loop.
// ---------------------------------------------------------------------------
__global__ __launch_bounds__(256)
void deform_sample_staged(const float* __restrict__ ref,     // [B,L,4,2]
                          const float* __restrict__ offlog,  // [B,L,384]
                          const float* __restrict__ val,     // [B,S,NH,HD]
                          float* __restrict__ acc_out) {     // [B,L,NH,HD]
    // [pair][sample][0..3]=u00,u10,u01,u11  [4..7]=corner elem offsets (int)
    __shared__ __align__(16) float sm[32][16][8];

    const int t = threadIdx.x;

    // ================= Phase 1: scalar prep =================
    {
        const int lp = t >> 3;                 // local pair 0..31
        const int gl = t & 7;                  // lane within pair
        const int P  = blockIdx.x * 32 + lp;   // global pair = bq*8 + h
        const int bq = P >> 3;
        const int h  = P & 7;

        const float* row = offlog + (size_t)bq * 384;

        // softmax over this head's 16 logits (2 per lane, 8 lanes/pair)
        const float2 x2 = *(const float2*)(row + 256 + h * 16 + gl * 2);
        float m = fmaxf(x2.x, x2.y);
#pragma unroll
        for (int o = 1; o < 8; o <<= 1)
            m = fmaxf(m, __shfl_xor_sync(0xffffffffu, m, o));
        const float ex = expf(x2.x - m);
        const float ey = expf(x2.y - m);
        float ssum = ex + ey;
#pragma unroll
        for (int o = 1; o < 8; o <<= 1)
            ssum += __shfl_xor_sync(0xffffffffu, ssum, o);
        const float inv = 1.f / ssum;
        const float wnx = ex * inv;
        const float wny = ey * inv;

        const float4 off4 = *(const float4*)(row + h * 32 + gl * 4);

        const int HH[4] = {100, 50, 25, 13};
        const int ST[4] = {0, 10000, 12500, 13125};
        const int l  = gl >> 1;                // level of both samples
        const int Wd = HH[l];
        const float Wf = (float)Wd;
        const int st = ST[l];

        const float2 rxy = *(const float2*)(ref + (size_t)bq * 8 + l * 2);

#pragma unroll
        for (int half = 0; half < 2; half++) {
            const int   s  = gl * 2 + half;
            const float ox = half ? off4.z : off4.x;
            const float oy = half ? off4.w : off4.y;
            const float ws = half ? wny    : wnx;

            const float xs = fmaf(rxy.x, Wf, ox) - 0.5f;
            const float ys = fmaf(rxy.y, Wf, oy) - 0.5f;
            const float x0f = floorf(xs);
            const float y0f = floorf(ys);
            const float fx = xs - x0f;
            const float fy = ys - y0f;
            const int x0 = (int)x0f;
            const int y0 = (int)y0f;
            const int x1 = x0 + 1;
            const int y1 = y0 + 1;

            const float gx0 = ((unsigned)x0 < (unsigned)Wd) ? (1.f - fx) : 0.f;
            const float gx1 = ((unsigned)x1 < (unsigned)Wd) ? fx         : 0.f;
            const float gy0 = ((unsigned)y0 < (unsigned)Wd) ? (1.f - fy) : 0.f;
            const float gy1 = ((unsigned)y1 < (unsigned)Wd) ? fy         : 0.f;

            const int x0c = min(max(x0, 0), Wd - 1);
            const int x1c = min(max(x1, 0), Wd - 1);
            const int y0c = min(max(y0, 0), Wd - 1);
            const int y1c = min(max(y1, 0), Wd - 1);

            const int r0 = st + y0c * Wd;
            const int r1 = st + y1c * Wd;

            float4 u4;
            u4.x = ws * gx0 * gy0;
            u4.y = ws * gx1 * gy0;
            u4.z = ws * gx0 * gy1;
            u4.w = ws * gx1 * gy1;

            float4 o4;
            o4.x = __int_as_float((r0 + x0c) * 256);
            o4.y = __int_as_float((r0 + x1c) * 256);
            o4.z = __int_as_float((r1 + x0c) * 256);
            o4.w = __int_as_float((r1 + x1c) * 256);

            *(float4*)&sm[lp][s][0] = u4;
            *(float4*)&sm[lp][s][4] = o4;
        }
    }

    __syncthreads();

    // ================= Phase 2: pure gather =================
    {
        const int warp = t >> 5;
        const int lane = t & 31;
        const int g    = lane >> 3;
        const int gl   = lane & 7;
        const int lp   = warp * 4 + g;
        const int P    = blockIdx.x * 32 + lp;
        const int bq   = P >> 3;
        const int h    = P & 7;
        const int b    = bq / L_;

        const float* vhead =
            val + (size_t)b * S_ * 256 + h * 32 + gl * 4;

        float4 acc = make_float4(0.f, 0.f, 0.f, 0.f);

#pragma unroll
        for (int s = 0; s < 16; s++) {
            const float4 u4 = *(const float4*)&sm[lp][s][0];
            const float4 of = *(const float4*)&sm[lp][s][4];

            const float4 v00 = *(const float4*)(vhead + __float_as_int(of.x));
            const float4 v10 = *(const float4*)(vhead + __float_as_int(of.y));
            const float4 v01 = *(const float4*)(vhead + __float_as_int(of.z));
            const float4 v11 = *(const float4*)(vhead + __float_as_int(of.w));

            acc.x += u4.x * v00.x + u4.y * v10.x + u4.z * v01.x + u4.w * v11.x;
            acc.y += u4.x * v00.y + u4.y * v10.y + u4.z * v01.y + u4.w * v11.y;
            acc.z += u4.x * v00.z + u4.y * v10.z + u4.z * v01.z + u4.w * v11.z;
            acc.w += u4.x * v00.w + u4.y * v10.w + u4.z * v01.w + u4.w * v11.w;
        }

        *(float4*)(acc_out + (size_t)bq * 256 + h * 32 + gl * 4) = acc;
    }
}

// ---------------------------------------------------------------------------
extern "C" void kernel_launch(void* const* d_in, const int* in_sizes, int n_in,
                              void* d_out, int out_size) {
    const float* query  = (const float*)d_in[0];
    const float* refpt  = (const float*)d_in[1];
    const float* value  = (const float*)d_in[2];
    const float* W_val  = (const float*)d_in[3];
    const float* b_val  = (const float*)d_in[4];
    const float* W_off  = (const float*)d_in[5];
    const float* b_off  = (const float*)d_in[6];
    const float* W_attn = (const float*)d_in[7];
    const float* b_attn = (const float*)d_in[8];
    const float* W_out  = (const float*)d_in[9];
    const float* b_out  = (const float*)d_in[10];
    float* out = (float*)d_out;

    float *val_s, *ol_s, *acc_s, *wc_s, *bc_s;
    cudaGetSymbolAddress((void**)&val_s, g_val);
    cudaGetSymbolAddress((void**)&ol_s,  g_offlog);
    cudaGetSymbolAddress((void**)&acc_s, g_acc);
    cudaGetSymbolAddress((void**)&wc_s,  g_Wcat);
    cudaGetSymbolAddress((void**)&bc_s,  g_bcat);

    const int M = M_;
    dim3 blk(256);
    dim3 gN256(2, (M + 127) / 128);
    dim3 gN384(3, (M + 127) / 128);

    // Pack fused query-projection weights (tiny)
    pack_qkw<<<(256 * 384) / 256, 256>>>(W_off, W_attn, b_off, b_attn, wc_s, bc_s);

    // Projections (tf32 tensor cores)
    gemm_tf32<<<gN256, blk>>>(value, W_val, b_val, val_s, M, 256, 256);
    gemm_tf32<<<gN384, blk>>>(query, wc_s, bc_s, ol_s, M, 384, 256);

    // Staged deformable sampling: 32 pairs per block, exact grid
    deform_sample_staged<<<(M_ * NH_) / 32, 256>>>(refpt, ol_s, val_s, acc_s);

    // Output projection -> d_out (tf32 tensor cores)
    gemm_tf32<<<gN256, blk>>>(acc_s, W_out, b_out, out, M, 256, 256);
}

// round 12
// speedup vs baseline: 1.1462x; 1.1462x over previous
#include <cuda_runtime.h>
#include <cuda_fp16.h>
#include <math.h>
#include <stdint.h>

// Problem constants
#define B_    2
#define L_    13294
#define S_    13294
#define NH_   8
#define M_    (B_ * L_)          // 26588 rows for all GEMMs

// Scratch (static device arrays — no allocation allowed)
__device__ float g_val   [(size_t)M_ * 256];  // value @ W_val    [B,S,NH,HD]
__device__ float g_offlog[(size_t)M_ * 384];  // query @ [W_off|W_attn]
__device__ float g_acc   [(size_t)M_ * 256];  // sampled output   [B,L,NH,HD]
__device__ float g_Wcat  [256 * 384];         // packed [W_off | W_attn] (K-major)
__device__ float g_bcat  [384];               // packed [b_off | b_attn]

// Pack two floats into one half2 register word (lo = a, hi = b).
__device__ __forceinline__ uint32_t pack2h(float a, float b) {
    uint32_t u;
    asm("cvt.rn.f16x2.f32 %0, %1, %2;" : "=r"(u) : "f"(b), "f"(a));
    return u;
}

// ---------------------------------------------------------------------------
// Pack [W_off | W_attn] (K=256 rows) and biases into contiguous N=384 buffers.
// ---------------------------------------------------------------------------
__global__ void pack_qkw(const float* __restrict__ W_off,
                         const float* __restrict__ W_attn,
                         const float* __restrict__ b_off,
                         const float* __restrict__ b_attn,
                         float* __restrict__ Wcat, float* __restrict__ bcat) {
    const int i = blockIdx.x * blockDim.x + threadIdx.x;   // 256*384 threads
    const int k = i / 384;
    const int n = i % 384;
    Wcat[i] = (n < 256) ? W_off[k * 256 + n] : W_attn[k * 128 + (n - 256)];
    if (i < 384)
        bcat[i] = (i < 256) ? b_off[i] : b_attn[i - 256];
}

// ---------------------------------------------------------------------------
// fp16 tensor-core GEMM with fp32 accumulate: C[M,N] = A[M,K] @ W[K,N] + b[N]
// Block tile 128x128, BK=16, 256 threads = 8 warps, warp tile 64x32.
// mma.sync.aligned.m16n8k16.row.col.f32.f16.f16.f32
// A staged as half2 words [row][kpair] stride 12 (banks 12g+tg distinct).
// B staged as half2 words [kpair][col] stride 136 (banks 8tg+g distinct);
// each B word packs (W[k][n], W[k+1][n]) so no weight transpose is needed.
// Double-buffered, one __syncthreads per K-iter. K%16==0, N%128==0; M guarded.
// ---------------------------------------------------------------------------
__global__ __launch_bounds__(256, 2)
void gemm_f16(const float* __restrict__ A, const float* __restrict__ W,
              const float* __restrict__ bias, float* __restrict__ C,
              int M, int N, int K) {
    __shared__ __align__(16) uint32_t As[2][128][12];  // [row][kpair(8 used)]
    __shared__ __align__(16) uint32_t Bs[2][8][136];   // [kpair][col(128 used)]

    const int t    = threadIdx.x;
    const int warp = t >> 5;
    const int lane = t & 31;
    const int g    = lane >> 2;         // 0..7
    const int tg   = lane & 3;          // 0..3
    const int wm   = (warp & 1) * 64;
    const int wn   = (warp >> 1) * 32;

    const int m0 = blockIdx.y * 128;
    const int n0 = blockIdx.x * 128;

    // A load mapping: thread -> (row, half of k16)
    const int arow  = t >> 1;           // 0..127
    const int ahalf = t & 1;            // k offset 0 or 8
    // B load mapping: thread -> (k-pair, 4 cols)
    const int bkp = t >> 5;             // 0..7
    const int bc4 = (t & 31) * 4;       // 0..124

    float4 av0, av1, bw0, bw1;

    auto load_tiles = [&](int k0) {
        const float4 z = make_float4(0.f, 0.f, 0.f, 0.f);
        const int r  = m0 + arow;
        const int ak = k0 + ahalf * 8;
        av0 = (r < M) ? *(const float4*)&A[(size_t)r * K + ak]     : z;
        av1 = (r < M) ? *(const float4*)&A[(size_t)r * K + ak + 4] : z;
        bw0 = *(const float4*)&W[(size_t)(k0 + 2 * bkp)     * N + n0 + bc4];
        bw1 = *(const float4*)&W[(size_t)(k0 + 2 * bkp + 1) * N + n0 + bc4];
    };
    auto store_tiles = [&](int buf) {
        // A: 8 consecutive k-floats -> 4 half2 words {k, k+1}
        uint4 a4;
        a4.x = pack2h(av0.x, av0.y);
        a4.y = pack2h(av0.z, av0.w);
        a4.z = pack2h(av1.x, av1.y);
        a4.w = pack2h(av1.z, av1.w);
        *(uint4*)&As[buf][arow][ahalf * 4] = a4;
        // B: pack (W[k][n], W[k+1][n]) per column
        uint4 b4;
        b4.x = pack2h(bw0.x, bw1.x);
        b4.y = pack2h(bw0.y, bw1.y);
        b4.z = pack2h(bw0.z, bw1.z);
        b4.w = pack2h(bw0.w, bw1.w);
        *(uint4*)&Bs[buf][bkp][bc4] = b4;
    };

    float acc[4][4][4];
#pragma unroll
    for (int i = 0; i < 4; i++)
#pragma unroll
        for (int j = 0; j < 4; j++)
#pragma unroll
            for (int r = 0; r < 4; r++) acc[i][j][r] = 0.f;

    const int niter = K / 16;
    load_tiles(0);
    store_tiles(0);
    __syncthreads();

    for (int it = 0; it < niter; ++it) {
        const int  buf  = it & 1;
        const bool more = (it + 1) < niter;
        if (more) load_tiles((it + 1) * 16);

        uint32_t af[4][4], bf[4][2];
#pragma unroll
        for (int mt = 0; mt < 4; mt++) {
            const int r = wm + mt * 16 + g;
            af[mt][0] = As[buf][r    ][tg];       // row g,   k 2tg,2tg+1
            af[mt][1] = As[buf][r + 8][tg];       // row g+8, k 2tg,2tg+1
            af[mt][2] = As[buf][r    ][tg + 4];   // row g,   k 2tg+8,2tg+9
            af[mt][3] = As[buf][r + 8][tg + 4];   // row g+8, k 2tg+8,2tg+9
        }
#pragma unroll
        for (int nt = 0; nt < 4; nt++) {
            const int c = wn + nt * 8 + g;
            bf[nt][0] = Bs[buf][tg    ][c];       // k 2tg,2tg+1,   col c
            bf[nt][1] = Bs[buf][tg + 4][c];       // k 2tg+8,2tg+9, col c
        }
#pragma unroll
        for (int mt = 0; mt < 4; mt++)
#pragma unroll
            for (int nt = 0; nt < 4; nt++) {
                asm volatile(
                    "mma.sync.aligned.m16n8k16.row.col.f32.f16.f16.f32 "
                    "{%0,%1,%2,%3}, {%4,%5,%6,%7}, {%8,%9}, {%0,%1,%2,%3};"
                    : "+f"(acc[mt][nt][0]), "+f"(acc[mt][nt][1]),
                      "+f"(acc[mt][nt][2]), "+f"(acc[mt][nt][3])
                    : "r"(af[mt][0]), "r"(af[mt][1]),
                      "r"(af[mt][2]), "r"(af[mt][3]),
                      "r"(bf[nt][0]), "r"(bf[nt][1]));
            }

        if (more) store_tiles(buf ^ 1);
        __syncthreads();
    }

    // Epilogue: bias add + store
#pragma unroll
    for (int nt = 0; nt < 4; nt++) {
        const int c = n0 + wn + nt * 8 + tg * 2;
        const float2 bb = *(const float2*)&bias[c];
#pragma unroll
        for (int mt = 0; mt < 4; mt++) {
            const int r0 = m0 + wm + mt * 16 + g;
            if (r0 < M) {
                float2 o = make_float2(acc[mt][nt][0] + bb.x,
                                       acc[mt][nt][1] + bb.y);
                *(float2*)&C[(size_t)r0 * N + c] = o;
            }
            const int r1 = r0 + 8;
            if (r1 < M) {
                float2 o = make_float2(acc[mt][nt][2] + bb.x,
                                       acc[mt][nt][3] + bb.y);
                *(float2*)&C[(size_t)r1 * N + c] = o;
            }
        }
    }
}

// ---------------------------------------------------------------------------
// Deformable sampling, 4-heads-per-warp (best-measured version, ~100us).
// ---------------------------------------------------------------------------
__global__ __launch_bounds__(256, 5)
void deform_sample4(const float* __restrict__ ref,     // [B,L,4,2]
                    const float* __restrict__ offlog,  // [B,L,384]
                    const float* __restrict__ val,     // [B,S,NH,HD]
                    float* __restrict__ acc_out) {     // [B,L,NH,HD]
    const int warp = blockIdx.x * 8 + (threadIdx.x >> 5);
    const int lane = threadIdx.x & 31;
    if (warp >= M_ * 2) return;

    const int bq = warp >> 1;
    const int b  = bq / L_;
    const int g  = lane >> 3;
    const int gl = lane & 7;
    const int h  = (warp & 1) * 4 + g;
    const int ch = gl * 4;

    const float* row = offlog + (size_t)bq * 384;

    const float2 x2 = *(const float2*)(row + 256 + h * 16 + gl * 2);
    float m = fmaxf(x2.x, x2.y);
#pragma unroll
    for (int o = 1; o < 8; o <<= 1)
        m = fmaxf(m, __shfl_xor_sync(0xffffffffu, m, o));
    const float ex = expf(x2.x - m);
    const float ey = expf(x2.y - m);
    float ssum = ex + ey;
#pragma unroll
    for (int o = 1; o < 8; o <<= 1)
        ssum += __shfl_xor_sync(0xffffffffu, ssum, o);
    const float inv = 1.f / ssum;
    const float wnx = ex * inv;
    const float wny = ey * inv;

    const float4 off4 = *(const float4*)(row + h * 32 + gl * 4);

    const float* rp = ref + (size_t)bq * 8;
    const float4 r01 = *(const float4*)rp;
    const float4 r23 = *(const float4*)(rp + 4);
    const float rx_[4] = {r01.x, r01.z, r23.x, r23.z};
    const float ry_[4] = {r01.y, r01.w, r23.y, r23.w};

    const int HH[4] = {100, 50, 25, 13};
    const int ST[4] = {0, 10000, 12500, 13125};

    const float* vhead = val + (size_t)b * S_ * 256 + h * 32 + ch;

    float4 acc = make_float4(0.f, 0.f, 0.f, 0.f);
    const float4 z4 = make_float4(0.f, 0.f, 0.f, 0.f);

#pragma unroll
    for (int l = 0; l < 4; l++) {
        const int   Wd = HH[l];
        const float Wf = (float)Wd;
        const float rx = rx_[l];
        const float ry = ry_[l];
        const float* vrow = vhead + ST[l] * 256;

#pragma unroll
        for (int p = 0; p < 4; p++) {
            const int s   = l * 4 + p;
            const int src = s >> 1;
            float ox, oy, ws;
            if ((s & 1) == 0) {
                ox = __shfl_sync(0xffffffffu, off4.x, src, 8);
                oy = __shfl_sync(0xffffffffu, off4.y, src, 8);
                ws = __shfl_sync(0xffffffffu, wnx,   src, 8);
            } else {
                ox = __shfl_sync(0xffffffffu, off4.z, src, 8);
                oy = __shfl_sync(0xffffffffu, off4.w, src, 8);
                ws = __shfl_sync(0xffffffffu, wny,   src, 8);
            }

            const float xs = fmaf(rx, Wf, ox) - 0.5f;
            const float ys = fmaf(ry, Wf, oy) - 0.5f;
            const float x0f = floorf(xs);
            const float y0f = floorf(ys);
            const float fx = xs - x0f;
            const float fy = ys - y0f;
            const int x0 = (int)x0f;
            const int y0 = (int)y0f;

            const bool okx0 = (unsigned)x0       < (unsigned)Wd;
            const bool okx1 = (unsigned)(x0 + 1) < (unsigned)Wd;
            const bool oky0 = (unsigned)y0       < (unsigned)Wd;
            const bool oky1 = (unsigned)(y0 + 1) < (unsigned)Wd;

            const float gx0 = 1.f - fx;
            const float gy0 = 1.f - fy;
            const float u00 = ws * gx0 * gy0;
            const float u10 = ws * fx  * gy0;
            const float u01 = ws * gx0 * fy;
            const float u11 = ws * fx  * fy;

            const float* p00 = vrow + (y0 * Wd + x0) * 256;

            const float4 v00 = (okx0 && oky0) ? *(const float4*)(p00)                  : z4;
            const float4 v10 = (okx1 && oky0) ? *(const float4*)(p00 + 256)            : z4;
            const float4 v01 = (okx0 && oky1) ? *(const float4*)(p00 + Wd * 256)       : z4;
            const float4 v11 = (okx1 && oky1) ? *(const float4*)(p00 + Wd * 256 + 256) : z4;

            acc.x += u00 * v00.x + u10 * v10.x + u01 * v01.x + u11 * v11.x;
            acc.y += u00 * v00.y + u10 * v10.y + u01 * v01.y + u11 * v11.y;
            acc.z += u00 * v00.z + u10 * v10.z + u01 * v01.z + u11 * v11.z;
            acc.w += u00 * v00.w + u10 * v10.w + u01 * v01.w + u11 * v11.w;
        }
    }

    *(float4*)(acc_out + (size_t)bq * 256 + h * 32 + ch) = acc;
}

// ---------------------------------------------------------------------------
extern "C" void kernel_launch(void* const* d_in, const int* in_sizes, int n_in,
                              void* d_out, int out_size) {
    const float* query  = (const float*)d_in[0];
    const float* refpt  = (const float*)d_in[1];
    const float* value  = (const float*)d_in[2];
    const float* W_val  = (const float*)d_in[3];
    const float* b_val  = (const float*)d_in[4];
    const float* W_off  = (const float*)d_in[5];
    const float* b_off  = (const float*)d_in[6];
    const float* W_attn = (const float*)d_in[7];
    const float* b_attn = (const float*)d_in[8];
    const float* W_out  = (const float*)d_in[9];
    const float* b_out  = (const float*)d_in[10];
    float* out = (float*)d_out;

    float *val_s, *ol_s, *acc_s, *wc_s, *bc_s;
    cudaGetSymbolAddress((void**)&val_s, g_val);
    cudaGetSymbolAddress((void**)&ol_s,  g_offlog);
    cudaGetSymbolAddress((void**)&acc_s, g_acc);
    cudaGetSymbolAddress((void**)&wc_s,  g_Wcat);
    cudaGetSymbolAddress((void**)&bc_s,  g_bcat);

    const int M = M_;
    dim3 blk(256);
    dim3 gN256(2, (M + 127) / 128);
    dim3 gN384(3, (M + 127) / 128);

    // Pack fused query-projection weights (tiny)
    pack_qkw<<<(256 * 384) / 256, 256>>>(W_off, W_attn, b_off, b_attn, wc_s, bc_s);

    // Projections (fp16 tensor cores, fp32 accumulate)
    gemm_f16<<<gN256, blk>>>(value, W_val, b_val, val_s, M, 256, 256);
    gemm_f16<<<gN384, blk>>>(query, wc_s, bc_s, ol_s, M, 384, 256);

    // Deformable sampling: one warp per (b,q, head-quad)
    deform_sample4<<<(M_ * 2 + 7) / 8, 256>>>(refpt, ol_s, val_s, acc_s);

    // Output projection -> d_out
    gemm_f16<<<gN256, blk>>>(acc_s, W_out, b_out, out, M, 256, 256);
}

// round 13
// speedup vs baseline: 1.3012x; 1.1352x over previous
#include <cuda_runtime.h>
#include <cuda_fp16.h>
#include <math.h>
#include <stdint.h>

// Problem constants
#define B_    2
#define L_    13294
#define S_    13294
#define NH_   8
#define M_    (B_ * L_)          // 26588 rows for all GEMMs

// Scratch (static device arrays — no allocation allowed)
__device__ __half g_val_h [(size_t)M_ * 256];  // value @ W_val  (fp16)
__device__ float  g_offlog[(size_t)M_ * 384];  // query @ [W_off|W_attn]
__device__ __half g_acc_h [(size_t)M_ * 256];  // sampled output (fp16)
__device__ float  g_Wcat  [256 * 384];         // packed [W_off | W_attn]
__device__ float  g_bcat  [384];               // packed [b_off | b_attn]

// Pack two floats into one half2 word (lo = a, hi = b).
__device__ __forceinline__ uint32_t pack2h(float a, float b) {
    uint32_t u;
    asm("cvt.rn.f16x2.f32 %0, %1, %2;" : "=r"(u) : "f"(b), "f"(a));
    return u;
}
// Load 4 consecutive halves, convert to float4.
__device__ __forceinline__ float4 ldh4(const __half* p) {
    const uint2 u = *(const uint2*)p;
    const __half2 h0 = *reinterpret_cast<const __half2*>(&u.x);
    const __half2 h1 = *reinterpret_cast<const __half2*>(&u.y);
    const float2 f0 = __half22float2(h0);
    const float2 f1 = __half22float2(h1);
    return make_float4(f0.x, f0.y, f1.x, f1.y);
}

// ---------------------------------------------------------------------------
// Pack [W_off | W_attn] (K=256 rows) and biases into contiguous N=384 buffers.
// ---------------------------------------------------------------------------
__global__ void pack_qkw(const float* __restrict__ W_off,
                         const float* __restrict__ W_attn,
                         const float* __restrict__ b_off,
                         const float* __restrict__ b_attn,
                         float* __restrict__ Wcat, float* __restrict__ bcat) {
    const int i = blockIdx.x * blockDim.x + threadIdx.x;   // 256*384 threads
    const int k = i / 384;
    const int n = i % 384;
    Wcat[i] = (n < 256) ? W_off[k * 256 + n] : W_attn[k * 128 + (n - 256)];
    if (i < 384)
        bcat[i] = (i < 256) ? b_off[i] : b_attn[i - 256];
}

// ---------------------------------------------------------------------------
// fp16 tensor-core GEMM, fp32 accumulate: C = A @ W + b.
// Template: AH = A is fp16 (direct stage, no cvt); CH = C stored as fp16.
// Block tile 128x128, BK=16, 256 threads, warp tile 64x32,
// mma.sync.aligned.m16n8k16.row.col.f32.f16.f16.f32, double-buffered smem.
// ---------------------------------------------------------------------------
template <bool AH, bool CH>
__global__ __launch_bounds__(256, 2)
void gemm_f16_t(const void* __restrict__ Av, const float* __restrict__ W,
                const float* __restrict__ bias, void* __restrict__ Cv,
                int M, int N, int K) {
    __shared__ __align__(16) uint32_t As[2][128][12];  // [row][kpair(8 used)]
    __shared__ __align__(16) uint32_t Bs[2][8][136];   // [kpair][col(128 used)]

    const int t    = threadIdx.x;
    const int warp = t >> 5;
    const int lane = t & 31;
    const int g    = lane >> 2;
    const int tg   = lane & 3;
    const int wm   = (warp & 1) * 64;
    const int wn   = (warp >> 1) * 32;

    const int m0 = blockIdx.y * 128;
    const int n0 = blockIdx.x * 128;

    const int arow  = t >> 1;           // 0..127
    const int ahalf = t & 1;            // k offset 0 or 8
    const int bkp   = t >> 5;           // 0..7
    const int bc4   = (t & 31) * 4;     // 0..124

    float4 av0, av1, bw0, bw1;
    uint4  ah4;

    auto load_tiles = [&](int k0) {
        const int r  = m0 + arow;
        const int ak = k0 + ahalf * 8;
        if (AH) {
            const __half* A = (const __half*)Av;
            ah4 = (r < M) ? *(const uint4*)&A[(size_t)r * K + ak]
                          : make_uint4(0u, 0u, 0u, 0u);
        } else {
            const float* A = (const float*)Av;
            const float4 z = make_float4(0.f, 0.f, 0.f, 0.f);
            av0 = (r < M) ? *(const float4*)&A[(size_t)r * K + ak]     : z;
            av1 = (r < M) ? *(const float4*)&A[(size_t)r * K + ak + 4] : z;
        }
        bw0 = *(const float4*)&W[(size_t)(k0 + 2 * bkp)     * N + n0 + bc4];
        bw1 = *(const float4*)&W[(size_t)(k0 + 2 * bkp + 1) * N + n0 + bc4];
    };
    auto store_tiles = [&](int buf) {
        uint4 a4;
        if (AH) {
            a4 = ah4;                   // memory order == (k,k+1) pair order
        } else {
            a4.x = pack2h(av0.x, av0.y);
            a4.y = pack2h(av0.z, av0.w);
            a4.z = pack2h(av1.x, av1.y);
            a4.w = pack2h(av1.z, av1.w);
        }
        *(uint4*)&As[buf][arow][ahalf * 4] = a4;
        uint4 b4;
        b4.x = pack2h(bw0.x, bw1.x);
        b4.y = pack2h(bw0.y, bw1.y);
        b4.z = pack2h(bw0.z, bw1.z);
        b4.w = pack2h(bw0.w, bw1.w);
        *(uint4*)&Bs[buf][bkp][bc4] = b4;
    };

    float acc[4][4][4];
#pragma unroll
    for (int i = 0; i < 4; i++)
#pragma unroll
        for (int j = 0; j < 4; j++)
#pragma unroll
            for (int r = 0; r < 4; r++) acc[i][j][r] = 0.f;

    const int niter = K / 16;
    load_tiles(0);
    store_tiles(0);
    __syncthreads();

    for (int it = 0; it < niter; ++it) {
        const int  buf  = it & 1;
        const bool more = (it + 1) < niter;
        if (more) load_tiles((it + 1) * 16);

        uint32_t af[4][4], bf[4][2];
#pragma unroll
        for (int mt = 0; mt < 4; mt++) {
            const int r = wm + mt * 16 + g;
            af[mt][0] = As[buf][r    ][tg];
            af[mt][1] = As[buf][r + 8][tg];
            af[mt][2] = As[buf][r    ][tg + 4];
            af[mt][3] = As[buf][r + 8][tg + 4];
        }
#pragma unroll
        for (int nt = 0; nt < 4; nt++) {
            const int c = wn + nt * 8 + g;
            bf[nt][0] = Bs[buf][tg    ][c];
            bf[nt][1] = Bs[buf][tg + 4][c];
        }
#pragma unroll
        for (int mt = 0; mt < 4; mt++)
#pragma unroll
            for (int nt = 0; nt < 4; nt++) {
                asm volatile(
                    "mma.sync.aligned.m16n8k16.row.col.f32.f16.f16.f32 "
                    "{%0,%1,%2,%3}, {%4,%5,%6,%7}, {%8,%9}, {%0,%1,%2,%3};"
                    : "+f"(acc[mt][nt][0]), "+f"(acc[mt][nt][1]),
                      "+f"(acc[mt][nt][2]), "+f"(acc[mt][nt][3])
                    : "r"(af[mt][0]), "r"(af[mt][1]),
                      "r"(af[mt][2]), "r"(af[mt][3]),
                      "r"(bf[nt][0]), "r"(bf[nt][1]));
            }

        if (more) store_tiles(buf ^ 1);
        __syncthreads();
    }

    // Epilogue: bias add + store (fp32 float2 or fp16 half2)
#pragma unroll
    for (int nt = 0; nt < 4; nt++) {
        const int c = n0 + wn + nt * 8 + tg * 2;
        const float2 bb = *(const float2*)&bias[c];
#pragma unroll
        for (int mt = 0; mt < 4; mt++) {
            const int r0 = m0 + wm + mt * 16 + g;
            const int r1 = r0 + 8;
            if (CH) {
                __half* C = (__half*)Cv;
                if (r0 < M)
                    *(uint32_t*)&C[(size_t)r0 * N + c] =
                        pack2h(acc[mt][nt][0] + bb.x, acc[mt][nt][1] + bb.y);
                if (r1 < M)
                    *(uint32_t*)&C[(size_t)r1 * N + c] =
                        pack2h(acc[mt][nt][2] + bb.x, acc[mt][nt][3] + bb.y);
            } else {
                float* C = (float*)Cv;
                if (r0 < M) {
                    float2 o = make_float2(acc[mt][nt][0] + bb.x,
                                           acc[mt][nt][1] + bb.y);
                    *(float2*)&C[(size_t)r0 * N + c] = o;
                }
                if (r1 < M) {
                    float2 o = make_float2(acc[mt][nt][2] + bb.x,
                                           acc[mt][nt][3] + bb.y);
                    *(float2*)&C[(size_t)r1 * N + c] = o;
                }
            }
        }
    }
}

// ---------------------------------------------------------------------------
// Staged deformable sampling over fp16 value tensor.
// Block = 32 (bq,h) pairs, 256 threads.
// Phase 1: 8 lanes/pair prep 2 samples each: softmax-scaled OOB-zeroed
//   bilinear weights + clamped corner element-offsets -> smem.
// Phase 2: per sample 2x LDS.128 + 4x LDG.64 (fp16) + 8 cvt + 16 FFMA.
// Output stored fp16 (identical rounding to the GEMM's stage-time cvt).
// ---------------------------------------------------------------------------
__global__ __launch_bounds__(256)
void deform_sample_h(const float*  __restrict__ ref,     // [B,L,4,2]
                     const float*  __restrict__ offlog,  // [B,L,384]
                     const __half* __restrict__ val,     // [B,S,NH,HD] fp16
                     __half* __restrict__ acc_out) {     // [B,L,NH,HD] fp16
    __shared__ __align__(16) float sm[32][16][8];

    const int t = threadIdx.x;

    // ================= Phase 1: scalar prep =================
    {
        const int lp = t >> 3;                 // local pair 0..31
        const int gl = t & 7;                  // lane within pair
        const int P  = blockIdx.x * 32 + lp;   // global pair = bq*8 + h
        const int bq = P >> 3;
        const int h  = P & 7;

        const float* row = offlog + (size_t)bq * 384;

        const float2 x2 = *(const float2*)(row + 256 + h * 16 + gl * 2);
        float m = fmaxf(x2.x, x2.y);
#pragma unroll
        for (int o = 1; o < 8; o <<= 1)
            m = fmaxf(m, __shfl_xor_sync(0xffffffffu, m, o));
        const float ex = expf(x2.x - m);
        const float ey = expf(x2.y - m);
        float ssum = ex + ey;
#pragma unroll
        for (int o = 1; o < 8; o <<= 1)
            ssum += __shfl_xor_sync(0xffffffffu, ssum, o);
        const float inv = 1.f / ssum;
        const float wnx = ex * inv;
        const float wny = ey * inv;

        const float4 off4 = *(const float4*)(row + h * 32 + gl * 4);

        const int HH[4] = {100, 50, 25, 13};
        const int ST[4] = {0, 10000, 12500, 13125};
        const int l  = gl >> 1;
        const int Wd = HH[l];
        const float Wf = (float)Wd;
        const int st = ST[l];

        const float2 rxy = *(const float2*)(ref + (size_t)bq * 8 + l * 2);

#pragma unroll
        for (int half = 0; half < 2; half++) {
            const int   s  = gl * 2 + half;
            const float ox = half ? off4.z : off4.x;
            const float oy = half ? off4.w : off4.y;
            const float ws = half ? wny    : wnx;

            const float xs = fmaf(rxy.x, Wf, ox) - 0.5f;
            const float ys = fmaf(rxy.y, Wf, oy) - 0.5f;
            const float x0f = floorf(xs);
            const float y0f = floorf(ys);
            const float fx = xs - x0f;
            const float fy = ys - y0f;
            const int x0 = (int)x0f;
            const int y0 = (int)y0f;
            const int x1 = x0 + 1;
            const int y1 = y0 + 1;

            const float gx0 = ((unsigned)x0 < (unsigned)Wd) ? (1.f - fx) : 0.f;
            const float gx1 = ((unsigned)x1 < (unsigned)Wd) ? fx         : 0.f;
            const float gy0 = ((unsigned)y0 < (unsigned)Wd) ? (1.f - fy) : 0.f;
            const float gy1 = ((unsigned)y1 < (unsigned)Wd) ? fy         : 0.f;

            const int x0c = min(max(x0, 0), Wd - 1);
            const int x1c = min(max(x1, 0), Wd - 1);
            const int y0c = min(max(y0, 0), Wd - 1);
            const int y1c = min(max(y1, 0), Wd - 1);

            const int r0 = st + y0c * Wd;
            const int r1 = st + y1c * Wd;

            float4 u4;
            u4.x = ws * gx0 * gy0;
            u4.y = ws * gx1 * gy0;
            u4.z = ws * gx0 * gy1;
            u4.w = ws * gx1 * gy1;

            float4 o4;
            o4.x = __int_as_float((r0 + x0c) * 256);
            o4.y = __int_as_float((r0 + x1c) * 256);
            o4.z = __int_as_float((r1 + x0c) * 256);
            o4.w = __int_as_float((r1 + x1c) * 256);

            *(float4*)&sm[lp][s][0] = u4;
            *(float4*)&sm[lp][s][4] = o4;
        }
    }

    __syncthreads();

    // ================= Phase 2: fp16 gather =================
    {
        const int warp = t >> 5;
        const int lane = t & 31;
        const int g    = lane >> 3;
        const int gl   = lane & 7;
        const int lp   = warp * 4 + g;
        const int P    = blockIdx.x * 32 + lp;
        const int bq   = P >> 3;
        const int h    = P & 7;
        const int b    = bq / L_;

        const __half* vhead =
            val + (size_t)b * S_ * 256 + h * 32 + gl * 4;

        float4 acc = make_float4(0.f, 0.f, 0.f, 0.f);

#pragma unroll
        for (int s = 0; s < 16; s++) {
            const float4 u4 = *(const float4*)&sm[lp][s][0];
            const float4 of = *(const float4*)&sm[lp][s][4];

            const float4 v00 = ldh4(vhead + __float_as_int(of.x));
            const float4 v10 = ldh4(vhead + __float_as_int(of.y));
            const float4 v01 = ldh4(vhead + __float_as_int(of.z));
            const float4 v11 = ldh4(vhead + __float_as_int(of.w));

            acc.x += u4.x * v00.x + u4.y * v10.x + u4.z * v01.x + u4.w * v11.x;
            acc.y += u4.x * v00.y + u4.y * v10.y + u4.z * v01.y + u4.w * v11.y;
            acc.z += u4.x * v00.z + u4.y * v10.z + u4.z * v01.z + u4.w * v11.z;
            acc.w += u4.x * v00.w + u4.y * v10.w + u4.z * v01.w + u4.w * v11.w;
        }

        uint2 o;
        o.x = pack2h(acc.x, acc.y);
        o.y = pack2h(acc.z, acc.w);
        *(uint2*)(acc_out + (size_t)bq * 256 + h * 32 + gl * 4) = o;
    }
}

// ---------------------------------------------------------------------------
extern "C" void kernel_launch(void* const* d_in, const int* in_sizes, int n_in,
                              void* d_out, int out_size) {
    const float* query  = (const float*)d_in[0];
    const float* refpt  = (const float*)d_in[1];
    const float* value  = (const float*)d_in[2];
    const float* W_val  = (const float*)d_in[3];
    const float* b_val  = (const float*)d_in[4];
    const float* W_off  = (const float*)d_in[5];
    const float* b_off  = (const float*)d_in[6];
    const float* W_attn = (const float*)d_in[7];
    const float* b_attn = (const float*)d_in[8];
    const float* W_out  = (const float*)d_in[9];
    const float* b_out  = (const float*)d_in[10];
    float* out = (float*)d_out;

    __half *valh_s, *acch_s;
    float *ol_s, *wc_s, *bc_s;
    cudaGetSymbolAddress((void**)&valh_s, g_val_h);
    cudaGetSymbolAddress((void**)&ol_s,   g_offlog);
    cudaGetSymbolAddress((void**)&acch_s, g_acc_h);
    cudaGetSymbolAddress((void**)&wc_s,   g_Wcat);
    cudaGetSymbolAddress((void**)&bc_s,   g_bcat);

    const int M = M_;
    dim3 blk(256);
    dim3 gN256(2, (M + 127) / 128);
    dim3 gN384(3, (M + 127) / 128);

    // Pack fused query-projection weights (tiny)
    pack_qkw<<<(256 * 384) / 256, 256>>>(W_off, W_attn, b_off, b_attn, wc_s, bc_s);

    // Projections: value -> fp16 val; query -> fp32 offsets+logits
    gemm_f16_t<false, true ><<<gN256, blk>>>(value, W_val, b_val, valh_s, M, 256, 256);
    gemm_f16_t<false, false><<<gN384, blk>>>(query, wc_s, bc_s, ol_s, M, 384, 256);

    // Staged deformable sampling over fp16 values -> fp16 acc
    deform_sample_h<<<(M_ * NH_) / 32, 256>>>(refpt, ol_s, valh_s, acch_s);

    // Output projection (fp16 A direct) -> d_out fp32
    gemm_f16_t<true, false><<<gN256, blk>>>(acch_s, W_out, b_out, out, M, 256, 256);
}

// round 14
// speedup vs baseline: 1.4855x; 1.1417x over previous
#include <cuda_runtime.h>
#include <cuda_fp16.h>
#include <math.h>
#include <stdint.h>

// Problem constants
#define B_    2
#define L_    13294
#define S_    13294
#define NH_   8
#define M_    (B_ * L_)          // 26588 rows for all GEMMs
#define N4_   ((M_ * 256) / 4)   // float4 count per [M,256] tensor

// Scratch (static device arrays — no allocation allowed)
__device__ __half   g_vh    [(size_t)M_ * 256];  // value  (fp16 pre-cvt)
__device__ __half   g_qh    [(size_t)M_ * 256];  // query  (fp16 pre-cvt)
__device__ __half   g_val_h [(size_t)M_ * 256];  // value @ W_val   (fp16)
__device__ float    g_offlog[(size_t)M_ * 384];  // query @ [W_off|W_attn]
__device__ __half   g_acc_h [(size_t)M_ * 256];  // sampled output  (fp16)
__device__ uint32_t g_Wp_val[128 * 256];         // W_val  paired half2 [kp][n]
__device__ uint32_t g_Wp_cat[128 * 384];         // [W_off|W_attn] paired
__device__ uint32_t g_Wp_out[128 * 256];         // W_out  paired
__device__ float    g_bcat  [384];               // packed [b_off | b_attn]

// Pack two floats into one half2 word (lo = a, hi = b).
__device__ __forceinline__ uint32_t pack2h(float a, float b) {
    uint32_t u;
    asm("cvt.rn.f16x2.f32 %0, %1, %2;" : "=r"(u) : "f"(b), "f"(a));
    return u;
}
// Load 4 consecutive halves, convert to float4.
__device__ __forceinline__ float4 ldh4(const __half* p) {
    const uint2 u = *(const uint2*)p;
    const __half2 h0 = *reinterpret_cast<const __half2*>(&u.x);
    const __half2 h1 = *reinterpret_cast<const __half2*>(&u.y);
    const float2 f0 = __half22float2(h0);
    const float2 f1 = __half22float2(h1);
    return make_float4(f0.x, f0.y, f1.x, f1.y);
}

// ---------------------------------------------------------------------------
// Pre-convert value & query to fp16 (same rounding the GEMM stage did before).
// ---------------------------------------------------------------------------
__global__ __launch_bounds__(256)
void cvt2h(const float4* __restrict__ v, const float4* __restrict__ q,
           uint2* __restrict__ vh, uint2* __restrict__ qh) {
    const int i = blockIdx.x * 256 + threadIdx.x;
    if (i >= N4_) return;
    const float4 a = v[i];
    vh[i] = make_uint2(pack2h(a.x, a.y), pack2h(a.z, a.w));
    const float4 b = q[i];
    qh[i] = make_uint2(pack2h(b.x, b.y), pack2h(b.z, b.w));
}

// ---------------------------------------------------------------------------
// Pack weights into (k,k+1)-paired half2 words [kp][n]; pack biases.
// ---------------------------------------------------------------------------
__global__ __launch_bounds__(256)
void pack_w(const float* __restrict__ Wv, const float* __restrict__ Wo,
            const float* __restrict__ Wa, const float* __restrict__ Wu,
            const float* __restrict__ bo, const float* __restrict__ ba,
            uint32_t* __restrict__ Pv, uint32_t* __restrict__ Pc,
            uint32_t* __restrict__ Pu, float* __restrict__ bc) {
    const int i = blockIdx.x * 256 + threadIdx.x;   // 448*256 = 114688
    if (i < 32768) {
        const int kp = i >> 8, n = i & 255;
        Pv[i] = pack2h(Wv[(2 * kp) * 256 + n], Wv[(2 * kp + 1) * 256 + n]);
    } else if (i < 81920) {
        const int j = i - 32768;
        const int kp = j / 384, n = j % 384;
        const float lo = (n < 256) ? Wo[(2 * kp) * 256 + n]
                                   : Wa[(2 * kp) * 128 + (n - 256)];
        const float hi = (n < 256) ? Wo[(2 * kp + 1) * 256 + n]
                                   : Wa[(2 * kp + 1) * 128 + (n - 256)];
        Pc[j] = pack2h(lo, hi);
    } else {
        const int j = i - 81920;
        const int kp = j >> 8, n = j & 255;
        Pu[j] = pack2h(Wu[(2 * kp) * 256 + n], Wu[(2 * kp + 1) * 256 + n]);
    }
    if (i < 384) bc[i] = (i < 256) ? bo[i] : ba[i - 256];
}

// ---------------------------------------------------------------------------
// fp16 tensor-core GEMM, fp32 accumulate, cp.async 4-stage pipeline.
// C[M,N] = A[M,256] @ W + b, A fp16 row-major, W pre-paired [128][N] words.
// Block tile 128x128, BK=16 (16 iters), 256 threads, warp tile 64x32,
// mma.sync.aligned.m16n8k16.row.col.f32.f16.f16.f32.
// CH: store C as fp16 (else fp32).
// ---------------------------------------------------------------------------
#define STAGES 4
template <bool CH>
__global__ __launch_bounds__(256, 2)
void gemm_async(const __half* __restrict__ A, const uint32_t* __restrict__ Wp,
                const float* __restrict__ bias, void* __restrict__ Cv,
                int M, int N) {
    __shared__ __align__(16) uint32_t As[STAGES][128][12];  // [row][kpair]
    __shared__ __align__(16) uint32_t Bs[STAGES][8][136];   // [kpair][col]

    const int t    = threadIdx.x;
    const int warp = t >> 5;
    const int lane = t & 31;
    const int g    = lane >> 2;
    const int tg   = lane & 3;
    const int wm   = (warp & 1) * 64;
    const int wn   = (warp >> 1) * 32;

    const int m0 = blockIdx.y * 128;
    const int n0 = blockIdx.x * 128;

    const int arow  = t >> 1;           // 0..127
    const int ahalf = t & 1;            // k offset 0 or 8
    const int bkp   = t >> 5;           // 0..7
    const int bc4   = (t & 31) * 4;     // 0..124

    auto issue = [&](int st, int k0) {
        // A: 16B = 8 halves of row (k0+ahalf*8 .. +7)
        const int r = m0 + arow;
        const __half* asrc = A + (size_t)r * 256 + k0 + ahalf * 8;
        const uint32_t adst =
            (uint32_t)__cvta_generic_to_shared(&As[st][arow][ahalf * 4]);
        const int asz = (r < M) ? 16 : 0;
        asm volatile("cp.async.cg.shared.global [%0], [%1], 16, %2;"
                     :: "r"(adst), "l"(asrc), "r"(asz) : "memory");
        // B: 16B = 4 paired words at kpair row (k0/2 + bkp)
        const uint32_t* bsrc = Wp + (size_t)((k0 >> 1) + bkp) * N + n0 + bc4;
        const uint32_t bdst =
            (uint32_t)__cvta_generic_to_shared(&Bs[st][bkp][bc4]);
        asm volatile("cp.async.cg.shared.global [%0], [%1], 16;"
                     :: "r"(bdst), "l"(bsrc) : "memory");
    };

    float acc[4][4][4];
#pragma unroll
    for (int i = 0; i < 4; i++)
#pragma unroll
        for (int j = 0; j < 4; j++)
#pragma unroll
            for (int r = 0; r < 4; r++) acc[i][j][r] = 0.f;

    // Prologue: fill STAGES-1 stages
#pragma unroll
    for (int s = 0; s < STAGES - 1; s++) {
        issue(s, s * 16);
        asm volatile("cp.async.commit_group;" ::: "memory");
    }

    for (int it = 0; it < 16; ++it) {
        asm volatile("cp.async.wait_group %0;" :: "n"(STAGES - 2) : "memory");
        __syncthreads();

        const int nk = it + STAGES - 1;
        if (nk < 16) issue(nk & (STAGES - 1), nk * 16);
        asm volatile("cp.async.commit_group;" ::: "memory");

        const int buf = it & (STAGES - 1);
        uint32_t af[4][4], bf[4][2];
#pragma unroll
        for (int mt = 0; mt < 4; mt++) {
            const int r = wm + mt * 16 + g;
            af[mt][0] = As[buf][r    ][tg];
            af[mt][1] = As[buf][r + 8][tg];
            af[mt][2] = As[buf][r    ][tg + 4];
            af[mt][3] = As[buf][r + 8][tg + 4];
        }
#pragma unroll
        for (int nt = 0; nt < 4; nt++) {
            const int c = wn + nt * 8 + g;
            bf[nt][0] = Bs[buf][tg    ][c];
            bf[nt][1] = Bs[buf][tg + 4][c];
        }
#pragma unroll
        for (int mt = 0; mt < 4; mt++)
#pragma unroll
            for (int nt = 0; nt < 4; nt++) {
                asm volatile(
                    "mma.sync.aligned.m16n8k16.row.col.f32.f16.f16.f32 "
                    "{%0,%1,%2,%3}, {%4,%5,%6,%7}, {%8,%9}, {%0,%1,%2,%3};"
                    : "+f"(acc[mt][nt][0]), "+f"(acc[mt][nt][1]),
                      "+f"(acc[mt][nt][2]), "+f"(acc[mt][nt][3])
                    : "r"(af[mt][0]), "r"(af[mt][1]),
                      "r"(af[mt][2]), "r"(af[mt][3]),
                      "r"(bf[nt][0]), "r"(bf[nt][1]));
            }
    }

    // Epilogue: bias add + store (fp32 float2 or fp16 half2)
#pragma unroll
    for (int nt = 0; nt < 4; nt++) {
        const int c = n0 + wn + nt * 8 + tg * 2;
        const float2 bb = *(const float2*)&bias[c];
#pragma unroll
        for (int mt = 0; mt < 4; mt++) {
            const int r0 = m0 + wm + mt * 16 + g;
            const int r1 = r0 + 8;
            if (CH) {
                __half* C = (__half*)Cv;
                if (r0 < M)
                    *(uint32_t*)&C[(size_t)r0 * N + c] =
                        pack2h(acc[mt][nt][0] + bb.x, acc[mt][nt][1] + bb.y);
                if (r1 < M)
                    *(uint32_t*)&C[(size_t)r1 * N + c] =
                        pack2h(acc[mt][nt][2] + bb.x, acc[mt][nt][3] + bb.y);
            } else {
                float* C = (float*)Cv;
                if (r0 < M) {
                    float2 o = make_float2(acc[mt][nt][0] + bb.x,
                                           acc[mt][nt][1] + bb.y);
                    *(float2*)&C[(size_t)r0 * N + c] = o;
                }
                if (r1 < M) {
                    float2 o = make_float2(acc[mt][nt][2] + bb.x,
                                           acc[mt][nt][3] + bb.y);
                    *(float2*)&C[(size_t)r1 * N + c] = o;
                }
            }
        }
    }
}

// ---------------------------------------------------------------------------
// Staged deformable sampling over fp16 value tensor (R13, measured 78.5us).
// ---------------------------------------------------------------------------
__global__ __launch_bounds__(256)
void deform_sample_h(const float*  __restrict__ ref,     // [B,L,4,2]
                     const float*  __restrict__ offlog,  // [B,L,384]
                     const __half* __restrict__ val,     // [B,S,NH,HD] fp16
                     __half* __restrict__ acc_out) {     // [B,L,NH,HD] fp16
    __shared__ __align__(16) float sm[32][16][8];

    const int t = threadIdx.x;

    // ================= Phase 1: scalar prep =================
    {
        const int lp = t >> 3;
        const int gl = t & 7;
        const int P  = blockIdx.x * 32 + lp;
        const int bq = P >> 3;
        const int h  = P & 7;

        const float* row = offlog + (size_t)bq * 384;

        const float2 x2 = *(const float2*)(row + 256 + h * 16 + gl * 2);
        float m = fmaxf(x2.x, x2.y);
#pragma unroll
        for (int o = 1; o < 8; o <<= 1)
            m = fmaxf(m, __shfl_xor_sync(0xffffffffu, m, o));
        const float ex = expf(x2.x - m);
        const float ey = expf(x2.y - m);
        float ssum = ex + ey;
#pragma unroll
        for (int o = 1; o < 8; o <<= 1)
            ssum += __shfl_xor_sync(0xffffffffu, ssum, o);
        const float inv = 1.f / ssum;
        const float wnx = ex * inv;
        const float wny = ey * inv;

        const float4 off4 = *(const float4*)(row + h * 32 + gl * 4);

        const int HH[4] = {100, 50, 25, 13};
        const int ST[4] = {0, 10000, 12500, 13125};
        const int l  = gl >> 1;
        const int Wd = HH[l];
        const float Wf = (float)Wd;
        const int st = ST[l];

        const float2 rxy = *(const float2*)(ref + (size_t)bq * 8 + l * 2);

#pragma unroll
        for (int half = 0; half < 2; half++) {
            const int   s  = gl * 2 + half;
            const float ox = half ? off4.z : off4.x;
            const float oy = half ? off4.w : off4.y;
            const float ws = half ? wny    : wnx;

            const float xs = fmaf(rxy.x, Wf, ox) - 0.5f;
            const float ys = fmaf(rxy.y, Wf, oy) - 0.5f;
            const float x0f = floorf(xs);
            const float y0f = floorf(ys);
            const float fx = xs - x0f;
            const float fy = ys - y0f;
            const int x0 = (int)x0f;
            const int y0 = (int)y0f;
            const int x1 = x0 + 1;
            const int y1 = y0 + 1;

            const float gx0 = ((unsigned)x0 < (unsigned)Wd) ? (1.f - fx) : 0.f;
            const float gx1 = ((unsigned)x1 < (unsigned)Wd) ? fx         : 0.f;
            const float gy0 = ((unsigned)y0 < (unsigned)Wd) ? (1.f - fy) : 0.f;
            const float gy1 = ((unsigned)y1 < (unsigned)Wd) ? fy         : 0.f;

            const int x0c = min(max(x0, 0), Wd - 1);
            const int x1c = min(max(x1, 0), Wd - 1);
            const int y0c = min(max(y0, 0), Wd - 1);
            const int y1c = min(max(y1, 0), Wd - 1);

            const int r0 = st + y0c * Wd;
            const int r1 = st + y1c * Wd;

            float4 u4;
            u4.x = ws * gx0 * gy0;
            u4.y = ws * gx1 * gy0;
            u4.z = ws * gx0 * gy1;
            u4.w = ws * gx1 * gy1;

            float4 o4;
            o4.x = __int_as_float((r0 + x0c) * 256);
            o4.y = __int_as_float((r0 + x1c) * 256);
            o4.z = __int_as_float((r1 + x0c) * 256);
            o4.w = __int_as_float((r1 + x1c) * 256);

            *(float4*)&sm[lp][s][0] = u4;
            *(float4*)&sm[lp][s][4] = o4;
        }
    }

    __syncthreads();

    // ================= Phase 2: fp16 gather =================
    {
        const int warp = t >> 5;
        const int lane = t & 31;
        const int g    = lane >> 3;
        const int gl   = lane & 7;
        const int lp   = warp * 4 + g;
        const int P    = blockIdx.x * 32 + lp;
        const int bq   = P >> 3;
        const int h    = P & 7;
        const int b    = bq / L_;

        const __half* vhead =
            val + (size_t)b * S_ * 256 + h * 32 + gl * 4;

        float4 acc = make_float4(0.f, 0.f, 0.f, 0.f);

#pragma unroll
        for (int s = 0; s < 16; s++) {
            const float4 u4 = *(const float4*)&sm[lp][s][0];
            const float4 of = *(const float4*)&sm[lp][s][4];

            const float4 v00 = ldh4(vhead + __float_as_int(of.x));
            const float4 v10 = ldh4(vhead + __float_as_int(of.y));
            const float4 v01 = ldh4(vhead + __float_as_int(of.z));
            const float4 v11 = ldh4(vhead + __float_as_int(of.w));

            acc.x += u4.x * v00.x + u4.y * v10.x + u4.z * v01.x + u4.w * v11.x;
            acc.y += u4.x * v00.y + u4.y * v10.y + u4.z * v01.y + u4.w * v11.y;
            acc.z += u4.x * v00.z + u4.y * v10.z + u4.z * v01.z + u4.w * v11.z;
            acc.w += u4.x * v00.w + u4.y * v10.w + u4.z * v01.w + u4.w * v11.w;
        }

        uint2 o;
        o.x = pack2h(acc.x, acc.y);
        o.y = pack2h(acc.z, acc.w);
        *(uint2*)(acc_out + (size_t)bq * 256 + h * 32 + gl * 4) = o;
    }
}

// ---------------------------------------------------------------------------
extern "C" void kernel_launch(void* const* d_in, const int* in_sizes, int n_in,
                              void* d_out, int out_size) {
    const float* query  = (const float*)d_in[0];
    const float* refpt  = (const float*)d_in[1];
    const float* value  = (const float*)d_in[2];
    const float* W_val  = (const float*)d_in[3];
    const float* b_val  = (const float*)d_in[4];
    const float* W_off  = (const float*)d_in[5];
    const float* b_off  = (const float*)d_in[6];
    const float* W_attn = (const float*)d_in[7];
    const float* b_attn = (const float*)d_in[8];
    const float* W_out  = (const float*)d_in[9];
    const float* b_out  = (const float*)d_in[10];
    float* out = (float*)d_out;

    __half *vh_s, *qh_s, *valh_s, *acch_s;
    float *ol_s, *bc_s;
    uint32_t *pv_s, *pc_s, *pu_s;
    cudaGetSymbolAddress((void**)&vh_s,   g_vh);
    cudaGetSymbolAddress((void**)&qh_s,   g_qh);
    cudaGetSymbolAddress((void**)&valh_s, g_val_h);
    cudaGetSymbolAddress((void**)&ol_s,   g_offlog);
    cudaGetSymbolAddress((void**)&acch_s, g_acc_h);
    cudaGetSymbolAddress((void**)&pv_s,   g_Wp_val);
    cudaGetSymbolAddress((void**)&pc_s,   g_Wp_cat);
    cudaGetSymbolAddress((void**)&pu_s,   g_Wp_out);
    cudaGetSymbolAddress((void**)&bc_s,   g_bcat);

    const int M = M_;
    dim3 blk(256);
    dim3 gN256(2, (M + 127) / 128);
    dim3 gN384(3, (M + 127) / 128);

    // Prep: fp16 conversion of value/query; paired-weight packing
    cvt2h<<<(N4_ + 255) / 256, 256>>>((const float4*)value, (const float4*)query,
                                      (uint2*)vh_s, (uint2*)qh_s);
    pack_w<<<448, 256>>>(W_val, W_off, W_attn, W_out, b_off, b_attn,
                         pv_s, pc_s, pu_s, bc_s);

    // Projections (cp.async 4-stage fp16 tensor-core GEMM)
    gemm_async<true ><<<gN256, blk>>>(vh_s, pv_s, b_val, valh_s, M, 256);
    gemm_async<false><<<gN384, blk>>>(qh_s, pc_s, bc_s, ol_s, M, 384);

    // Staged deformable sampling over fp16 values -> fp16 acc
    deform_sample_h<<<(M_ * NH_) / 32, 256>>>(refpt, ol_s, valh_s, acch_s);

    // Output projection (fp16 A direct) -> d_out fp32
    gemm_async<false><<<gN256, blk>>>(acch_s, pu_s, b_out, out, M, 256);
}

// round 15
// speedup vs baseline: 1.5962x; 1.0745x over previous
#include <cuda_runtime.h>
#include <cuda_fp16.h>
#include <math.h>
#include <stdint.h>

// Problem constants
#define B_    2
#define L_    13294
#define S_    13294
#define NH_   8
#define M_    (B_ * L_)          // 26588 rows for all GEMMs
#define N4_   ((M_ * 256) / 4)   // float4 count per [M,256] tensor

// Scratch (static device arrays — no allocation allowed)
__device__ __half   g_vh    [(size_t)M_ * 256];  // value  (fp16 pre-cvt)
__device__ __half   g_qh    [(size_t)M_ * 256];  // query  (fp16 pre-cvt)
__device__ __half   g_val_h [(size_t)M_ * 256];  // value @ W_val   (fp16)
__device__ float    g_offlog[(size_t)M_ * 384];  // query @ [W_off|W_attn]
__device__ __half   g_acc_h [(size_t)M_ * 256];  // sampled output  (fp16)
__device__ uint32_t g_Wp_val[256 * 128];         // W_val  paired  [n][kp]
__device__ uint32_t g_Wp_cat[384 * 128];         // [W_off|W_attn] [n][kp]
__device__ uint32_t g_Wp_out[256 * 128];         // W_out  paired  [n][kp]
__device__ float    g_bcat  [384];               // packed [b_off | b_attn]

// Pack two floats into one half2 word (lo = a, hi = b).
__device__ __forceinline__ uint32_t pack2h(float a, float b) {
    uint32_t u;
    asm("cvt.rn.f16x2.f32 %0, %1, %2;" : "=r"(u) : "f"(b), "f"(a));
    return u;
}
// Load 4 consecutive halves, convert to float4.
__device__ __forceinline__ float4 ldh4(const __half* p) {
    const uint2 u = *(const uint2*)p;
    const __half2 h0 = *reinterpret_cast<const __half2*>(&u.x);
    const __half2 h1 = *reinterpret_cast<const __half2*>(&u.y);
    const float2 f0 = __half22float2(h0);
    const float2 f1 = __half22float2(h1);
    return make_float4(f0.x, f0.y, f1.x, f1.y);
}
__device__ __forceinline__ void ldsm4(uint32_t& r0, uint32_t& r1,
                                      uint32_t& r2, uint32_t& r3,
                                      uint32_t addr) {
    asm volatile("ldmatrix.sync.aligned.m8n8.x4.shared.b16 {%0,%1,%2,%3}, [%4];"
                 : "=r"(r0), "=r"(r1), "=r"(r2), "=r"(r3) : "r"(addr));
}

// ---------------------------------------------------------------------------
// Pre-convert value & query to fp16.
// ---------------------------------------------------------------------------
__global__ __launch_bounds__(256)
void cvt2h(const float4* __restrict__ v, const float4* __restrict__ q,
           uint2* __restrict__ vh, uint2* __restrict__ qh) {
    const int i = blockIdx.x * 256 + threadIdx.x;
    if (i >= N4_) return;
    const float4 a = v[i];
    vh[i] = make_uint2(pack2h(a.x, a.y), pack2h(a.z, a.w));
    const float4 b = q[i];
    qh[i] = make_uint2(pack2h(b.x, b.y), pack2h(b.z, b.w));
}

// ---------------------------------------------------------------------------
// Pack weights into n-major (k,k+1)-paired half2 words [n][kp]; pack biases.
// ---------------------------------------------------------------------------
__global__ __launch_bounds__(256)
void pack_w(const float* __restrict__ Wv, const float* __restrict__ Wo,
            const float* __restrict__ Wa, const float* __restrict__ Wu,
            const float* __restrict__ bo, const float* __restrict__ ba,
            uint32_t* __restrict__ Pv, uint32_t* __restrict__ Pc,
            uint32_t* __restrict__ Pu, float* __restrict__ bc) {
    const int i = blockIdx.x * 256 + threadIdx.x;   // 448*256 = 114688
    if (i < 32768) {
        const int n = i >> 7, kp = i & 127;
        Pv[i] = pack2h(Wv[(2 * kp) * 256 + n], Wv[(2 * kp + 1) * 256 + n]);
    } else if (i < 81920) {
        const int j = i - 32768;
        const int n = j >> 7, kp = j & 127;
        const float lo = (n < 256) ? Wo[(2 * kp) * 256 + n]
                                   : Wa[(2 * kp) * 128 + (n - 256)];
        const float hi = (n < 256) ? Wo[(2 * kp + 1) * 256 + n]
                                   : Wa[(2 * kp + 1) * 128 + (n - 256)];
        Pc[j] = pack2h(lo, hi);
    } else {
        const int j = i - 81920;
        const int n = j >> 7, kp = j & 127;
        Pu[j] = pack2h(Wu[(2 * kp) * 256 + n], Wu[(2 * kp + 1) * 256 + n]);
    }
    if (i < 384) bc[i] = (i < 256) ? bo[i] : ba[i - 256];
}

// ---------------------------------------------------------------------------
// fp16 tensor-core GEMM, fp32 accumulate, cp.async 4-stage + ldmatrix.
// MODE 0: merged projection launch, grid.x=5 (bx<2: value N=256 ->fp16;
//         bx>=2: query N=384 ->fp32). MODE 1: output GEMM, grid.x=2, fp32.
// Block tile 128x128, BK=16 (16 iters), 256 threads, warp tile 64x32.
// A smem [128][12] words row-major kpairs; B smem [128][12] words n-major.
// ---------------------------------------------------------------------------
#define STG 4
#define STRIDE_B 6144   // 128*12*4 bytes per stage
template <int MODE>
__global__ __launch_bounds__(256, 2)
void gemm_lds(const __half* __restrict__ A0, const uint32_t* __restrict__ W0,
              const float* __restrict__ b0f, void* __restrict__ C0v,
              const __half* __restrict__ A1, const uint32_t* __restrict__ W1,
              const float* __restrict__ b1f, void* __restrict__ C1v) {
    __shared__ __align__(16) uint32_t As[STG][128][12];
    __shared__ __align__(16) uint32_t Bs[STG][128][12];

    const __half* A; const uint32_t* Wp; const float* bias; void* Cv;
    int N, n0; bool ch;
    if (MODE == 0) {
        if (blockIdx.x < 2) {
            A = A0; Wp = W0; bias = b0f; Cv = C0v;
            N = 256; n0 = blockIdx.x * 128; ch = true;
        } else {
            A = A1; Wp = W1; bias = b1f; Cv = C1v;
            N = 384; n0 = (blockIdx.x - 2) * 128; ch = false;
        }
    } else {
        A = A0; Wp = W0; bias = b0f; Cv = C0v;
        N = 256; n0 = blockIdx.x * 128; ch = false;
    }

    const int t    = threadIdx.x;
    const int warp = t >> 5;
    const int lane = t & 31;
    const int g    = lane >> 2;
    const int tg   = lane & 3;
    const int wm   = (warp & 1) * 64;
    const int wn   = (warp >> 1) * 32;
    const int m0   = blockIdx.y * 128;

    // cp.async source mappings
    const int arow  = t >> 1;            // A row 0..127
    const int ahalf = t & 1;             // A k-chunk 0/1
    const int bn    = t >> 1;            // B n-row 0..127
    const int bhalf = t & 1;             // B kp-chunk 0/1

    const uint32_t as0 = (uint32_t)__cvta_generic_to_shared(&As[0][0][0]);
    const uint32_t bs0 = (uint32_t)__cvta_generic_to_shared(&Bs[0][0][0]);
    const uint32_t adst0 = as0 + (arow * 12 + ahalf * 4) * 4;
    const uint32_t bdst0 = bs0 + (bn * 12 + bhalf * 4) * 4;

    // ldmatrix lane addresses (byte offsets within a stage)
    const int sub = lane >> 3;           // 0..3
    uint32_t a_off[4], b_off[2];
#pragma unroll
    for (int mt = 0; mt < 4; mt++) {
        const int r = wm + mt * 16 + (lane & 7) + ((sub & 1) * 8);
        a_off[mt] = as0 + (r * 12 + (sub >> 1) * 4) * 4;
    }
#pragma unroll
    for (int p = 0; p < 2; p++) {
        const int r = wn + p * 16 + (sub >> 1) * 8 + (lane & 7);
        b_off[p] = bs0 + (r * 12 + (sub & 1) * 4) * 4;
    }

    auto issue = [&](int st, int it) {
        const int r = m0 + arow;
        const __half* asrc = A + (size_t)r * 256 + it * 16 + ahalf * 8;
        const int asz = (r < M_) ? 16 : 0;
        asm volatile("cp.async.cg.shared.global [%0], [%1], 16, %2;"
                     :: "r"(adst0 + st * STRIDE_B), "l"(asrc), "r"(asz)
                     : "memory");
        const uint32_t* bsrc =
            Wp + (size_t)(n0 + bn) * 128 + it * 8 + bhalf * 4;
        asm volatile("cp.async.cg.shared.global [%0], [%1], 16;"
                     :: "r"(bdst0 + st * STRIDE_B), "l"(bsrc) : "memory");
    };

    float acc[4][4][4];
#pragma unroll
    for (int i = 0; i < 4; i++)
#pragma unroll
        for (int j = 0; j < 4; j++)
#pragma unroll
            for (int r = 0; r < 4; r++) acc[i][j][r] = 0.f;

#pragma unroll
    for (int s = 0; s < STG - 1; s++) {
        issue(s, s);
        asm volatile("cp.async.commit_group;" ::: "memory");
    }

#pragma unroll
    for (int it = 0; it < 16; ++it) {
        asm volatile("cp.async.wait_group %0;" :: "n"(STG - 2) : "memory");
        __syncthreads();

        const int nk = it + STG - 1;
        if (nk < 16) issue(nk & (STG - 1), nk);
        asm volatile("cp.async.commit_group;" ::: "memory");

        const uint32_t soff = (uint32_t)(it & (STG - 1)) * STRIDE_B;
        uint32_t af[4][4], bf[4][2];
#pragma unroll
        for (int mt = 0; mt < 4; mt++)
            ldsm4(af[mt][0], af[mt][1], af[mt][2], af[mt][3],
                  a_off[mt] + soff);
#pragma unroll
        for (int p = 0; p < 2; p++)
            ldsm4(bf[2 * p][0], bf[2 * p][1], bf[2 * p + 1][0],
                  bf[2 * p + 1][1], b_off[p] + soff);

#pragma unroll
        for (int mt = 0; mt < 4; mt++)
#pragma unroll
            for (int nt = 0; nt < 4; nt++) {
                asm volatile(
                    "mma.sync.aligned.m16n8k16.row.col.f32.f16.f16.f32 "
                    "{%0,%1,%2,%3}, {%4,%5,%6,%7}, {%8,%9}, {%0,%1,%2,%3};"
                    : "+f"(acc[mt][nt][0]), "+f"(acc[mt][nt][1]),
                      "+f"(acc[mt][nt][2]), "+f"(acc[mt][nt][3])
                    : "r"(af[mt][0]), "r"(af[mt][1]),
                      "r"(af[mt][2]), "r"(af[mt][3]),
                      "r"(bf[nt][0]), "r"(bf[nt][1]));
            }
    }

    // Epilogue: bias add + store
#pragma unroll
    for (int nt = 0; nt < 4; nt++) {
        const int c = n0 + wn + nt * 8 + tg * 2;
        const float2 bb = *(const float2*)&bias[c];
#pragma unroll
        for (int mt = 0; mt < 4; mt++) {
            const int r0 = m0 + wm + mt * 16 + g;
            const int r1 = r0 + 8;
            if (ch) {
                __half* C = (__half*)Cv;
                if (r0 < M_)
                    *(uint32_t*)&C[(size_t)r0 * N + c] =
                        pack2h(acc[mt][nt][0] + bb.x, acc[mt][nt][1] + bb.y);
                if (r1 < M_)
                    *(uint32_t*)&C[(size_t)r1 * N + c] =
                        pack2h(acc[mt][nt][2] + bb.x, acc[mt][nt][3] + bb.y);
            } else {
                float* C = (float*)Cv;
                if (r0 < M_) {
                    float2 o = make_float2(acc[mt][nt][0] + bb.x,
                                           acc[mt][nt][1] + bb.y);
                    *(float2*)&C[(size_t)r0 * N + c] = o;
                }
                if (r1 < M_) {
                    float2 o = make_float2(acc[mt][nt][2] + bb.x,
                                           acc[mt][nt][3] + bb.y);
                    *(float2*)&C[(size_t)r1 * N + c] = o;
                }
            }
        }
    }
}

// ---------------------------------------------------------------------------
// Staged deformable sampling over fp16 value tensor (R13, measured 78.5us).
// ---------------------------------------------------------------------------
__global__ __launch_bounds__(256)
void deform_sample_h(const float*  __restrict__ ref,
                     const float*  __restrict__ offlog,
                     const __half* __restrict__ val,
                     __half* __restrict__ acc_out) {
    __shared__ __align__(16) float sm[32][16][8];

    const int t = threadIdx.x;

    // Phase 1: scalar prep
    {
        const int lp = t >> 3;
        const int gl = t & 7;
        const int P  = blockIdx.x * 32 + lp;
        const int bq = P >> 3;
        const int h  = P & 7;

        const float* row = offlog + (size_t)bq * 384;

        const float2 x2 = *(const float2*)(row + 256 + h * 16 + gl * 2);
        float m = fmaxf(x2.x, x2.y);
#pragma unroll
        for (int o = 1; o < 8; o <<= 1)
            m = fmaxf(m, __shfl_xor_sync(0xffffffffu, m, o));
        const float ex = expf(x2.x - m);
        const float ey = expf(x2.y - m);
        float ssum = ex + ey;
#pragma unroll
        for (int o = 1; o < 8; o <<= 1)
            ssum += __shfl_xor_sync(0xffffffffu, ssum, o);
        const float inv = 1.f / ssum;
        const float wnx = ex * inv;
        const float wny = ey * inv;

        const float4 off4 = *(const float4*)(row + h * 32 + gl * 4);

        const int HH[4] = {100, 50, 25, 13};
        const int ST[4] = {0, 10000, 12500, 13125};
        const int l  = gl >> 1;
        const int Wd = HH[l];
        const float Wf = (float)Wd;
        const int st = ST[l];

        const float2 rxy = *(const float2*)(ref + (size_t)bq * 8 + l * 2);

#pragma unroll
        for (int half = 0; half < 2; half++) {
            const int   s  = gl * 2 + half;
            const float ox = half ? off4.z : off4.x;
            const float oy = half ? off4.w : off4.y;
            const float ws = half ? wny    : wnx;

            const float xs = fmaf(rxy.x, Wf, ox) - 0.5f;
            const float ys = fmaf(rxy.y, Wf, oy) - 0.5f;
            const float x0f = floorf(xs);
            const float y0f = floorf(ys);
            const float fx = xs - x0f;
            const float fy = ys - y0f;
            const int x0 = (int)x0f;
            const int y0 = (int)y0f;
            const int x1 = x0 + 1;
            const int y1 = y0 + 1;

            const float gx0 = ((unsigned)x0 < (unsigned)Wd) ? (1.f - fx) : 0.f;
            const float gx1 = ((unsigned)x1 < (unsigned)Wd) ? fx         : 0.f;
            const float gy0 = ((unsigned)y0 < (unsigned)Wd) ? (1.f - fy) : 0.f;
            const float gy1 = ((unsigned)y1 < (unsigned)Wd) ? fy         : 0.f;

            const int x0c = min(max(x0, 0), Wd - 1);
            const int x1c = min(max(x1, 0), Wd - 1);
            const int y0c = min(max(y0, 0), Wd - 1);
            const int y1c = min(max(y1, 0), Wd - 1);

            const int r0 = st + y0c * Wd;
            const int r1 = st + y1c * Wd;

            float4 u4;
            u4.x = ws * gx0 * gy0;
            u4.y = ws * gx1 * gy0;
            u4.z = ws * gx0 * gy1;
            u4.w = ws * gx1 * gy1;

            float4 o4;
            o4.x = __int_as_float((r0 + x0c) * 256);
            o4.y = __int_as_float((r0 + x1c) * 256);
            o4.z = __int_as_float((r1 + x0c) * 256);
            o4.w = __int_as_float((r1 + x1c) * 256);

            *(float4*)&sm[lp][s][0] = u4;
            *(float4*)&sm[lp][s][4] = o4;
        }
    }

    __syncthreads();

    // Phase 2: fp16 gather
    {
        const int warp = t >> 5;
        const int lane = t & 31;
        const int g    = lane >> 3;
        const int gl   = lane & 7;
        const int lp   = warp * 4 + g;
        const int P    = blockIdx.x * 32 + lp;
        const int bq   = P >> 3;
        const int h    = P & 7;
        const int b    = bq / L_;

        const __half* vhead =
            val + (size_t)b * S_ * 256 + h * 32 + gl * 4;

        float4 acc = make_float4(0.f, 0.f, 0.f, 0.f);

#pragma unroll
        for (int s = 0; s < 16; s++) {
            const float4 u4 = *(const float4*)&sm[lp][s][0];
            const float4 of = *(const float4*)&sm[lp][s][4];

            const float4 v00 = ldh4(vhead + __float_as_int(of.x));
            const float4 v10 = ldh4(vhead + __float_as_int(of.y));
            const float4 v01 = ldh4(vhead + __float_as_int(of.z));
            const float4 v11 = ldh4(vhead + __float_as_int(of.w));

            acc.x += u4.x * v00.x + u4.y * v10.x + u4.z * v01.x + u4.w * v11.x;
            acc.y += u4.x * v00.y + u4.y * v10.y + u4.z * v01.y + u4.w * v11.y;
            acc.z += u4.x * v00.z + u4.y * v10.z + u4.z * v01.z + u4.w * v11.z;
            acc.w += u4.x * v00.w + u4.y * v10.w + u4.z * v01.w + u4.w * v11.w;
        }

        uint2 o;
        o.x = pack2h(acc.x, acc.y);
        o.y = pack2h(acc.z, acc.w);
        *(uint2*)(acc_out + (size_t)bq * 256 + h * 32 + gl * 4) = o;
    }
}

// ---------------------------------------------------------------------------
extern "C" void kernel_launch(void* const* d_in, const int* in_sizes, int n_in,
                              void* d_out, int out_size) {
    const float* query  = (const float*)d_in[0];
    const float* refpt  = (const float*)d_in[1];
    const float* value  = (const float*)d_in[2];
    const float* W_val  = (const float*)d_in[3];
    const float* b_val  = (const float*)d_in[4];
    const float* W_off  = (const float*)d_in[5];
    const float* b_off  = (const float*)d_in[6];
    const float* W_attn = (const float*)d_in[7];
    const float* b_attn = (const float*)d_in[8];
    const float* W_out  = (const float*)d_in[9];
    const float* b_out  = (const float*)d_in[10];
    float* out = (float*)d_out;

    __half *vh_s, *qh_s, *valh_s, *acch_s;
    float *ol_s, *bc_s;
    uint32_t *pv_s, *pc_s, *pu_s;
    cudaGetSymbolAddress((void**)&vh_s,   g_vh);
    cudaGetSymbolAddress((void**)&qh_s,   g_qh);
    cudaGetSymbolAddress((void**)&valh_s, g_val_h);
    cudaGetSymbolAddress((void**)&ol_s,   g_offlog);
    cudaGetSymbolAddress((void**)&acch_s, g_acc_h);
    cudaGetSymbolAddress((void**)&pv_s,   g_Wp_val);
    cudaGetSymbolAddress((void**)&pc_s,   g_Wp_cat);
    cudaGetSymbolAddress((void**)&pu_s,   g_Wp_out);
    cudaGetSymbolAddress((void**)&bc_s,   g_bcat);

    const int MT = (M_ + 127) / 128;   // 208 row tiles
    dim3 blk(256);

    // Prep: fp16 conversion of value/query; n-major paired-weight packing
    cvt2h<<<(N4_ + 255) / 256, 256>>>((const float4*)value, (const float4*)query,
                                      (uint2*)vh_s, (uint2*)qh_s);
    pack_w<<<448, 256>>>(W_val, W_off, W_attn, W_out, b_off, b_attn,
                         pv_s, pc_s, pu_s, bc_s);

    // Merged projections: value->fp16 val (bx<2), query->fp32 offlog (bx>=2)
    gemm_lds<0><<<dim3(5, MT), blk>>>(vh_s, pv_s, b_val, valh_s,
                                      qh_s, pc_s, bc_s, ol_s);

    // Staged deformable sampling over fp16 values -> fp16 acc
    deform_sample_h<<<(M_ * NH_) / 32, 256>>>(refpt, ol_s, valh_s, acch_s);

    // Output projection -> d_out fp32
    gemm_lds<1><<<dim3(2, MT), blk>>>(acch_s, pu_s, b_out, out,
                                      (const __half*)nullptr,
                                      (const uint32_t*)nullptr,
                                      (const float*)nullptr, nullptr);
}